// round 2
// baseline (speedup 1.0000x reference)
#include <cuda_runtime.h>
#include <cuda_bf16.h>
#include <math.h>

// Problem constants
#define Bc 2
#define Tc 2048
#define Dc 2048
#define Hc 8
#define DKc 256
#define DVc 512
#define Cc 64
#define Nc 32          // T / C
#define Mrows 4096     // B*T

// ---------------------------------------------------------------------------
// Scratch (device globals; no allocation allowed)
// ---------------------------------------------------------------------------
__device__ float g_q[(size_t)Mrows * (Hc * DKc)];        //  33.5 MB
__device__ float g_k[(size_t)Mrows * (Hc * DKc)];        //  33.5 MB
__device__ float g_v[(size_t)Mrows * (Hc * DVc)];        //  67 MB
__device__ float g_g[(size_t)Mrows * (Hc * DVc)];        //  67 MB
__device__ float g_sc[(size_t)Bc * Hc * Nc * Cc * Cc];   //   8.4 MB
__device__ float g_S[(size_t)Bc * Hc * Nc * DKc * DVc];  // 268 MB (A_n then S-prefix, in place)
__device__ float g_o[(size_t)Mrows * (Hc * DVc)];        //  67 MB
__device__ float g_n[(size_t)Mrows * (Hc * DVc)];        //  67 MB

__device__ __forceinline__ float decay_logb(int h) {
    return logf(1.0f - exp2f(-5.0f - (float)h));
}

// ---------------------------------------------------------------------------
// Generic fp32 GEMM:  C[M,N] = A[M,K] @ B[N,K]^T   (both K-major, coalesced)
// 128x128 tile, BK=16, 256 threads, 8x8 per thread
// ---------------------------------------------------------------------------
__global__ __launch_bounds__(256) void gemm_abt(
    const float* __restrict__ A, const float* __restrict__ Bm,
    float* __restrict__ C, int M, int N, int K)
{
    __shared__ float As[16][132];
    __shared__ float Bs[16][132];
    const int tid = threadIdx.x;
    const int bm = blockIdx.y * 128;
    const int bn = blockIdx.x * 128;
    const int tx = tid & 15;     // n dir
    const int ty = tid >> 4;     // m dir
    float acc[8][8];
#pragma unroll
    for (int i = 0; i < 8; ++i)
#pragma unroll
        for (int j = 0; j < 8; ++j) acc[i][j] = 0.f;

    const int lrow = tid >> 2;          // 0..63
    const int lcol = (tid & 3) << 2;    // 0,4,8,12

    for (int k0 = 0; k0 < K; k0 += 16) {
#pragma unroll
        for (int r = 0; r < 2; ++r) {
            const int row = lrow + r * 64;
            float4 va = *(const float4*)(A + (size_t)(bm + row) * K + k0 + lcol);
            As[lcol + 0][row] = va.x; As[lcol + 1][row] = va.y;
            As[lcol + 2][row] = va.z; As[lcol + 3][row] = va.w;
            float4 vb = *(const float4*)(Bm + (size_t)(bn + row) * K + k0 + lcol);
            Bs[lcol + 0][row] = vb.x; Bs[lcol + 1][row] = vb.y;
            Bs[lcol + 2][row] = vb.z; Bs[lcol + 3][row] = vb.w;
        }
        __syncthreads();
#pragma unroll
        for (int kk = 0; kk < 16; ++kk) {
            float ra[8], rb[8];
            *(float4*)&ra[0] = *(const float4*)&As[kk][ty * 8];
            *(float4*)&ra[4] = *(const float4*)&As[kk][ty * 8 + 4];
            *(float4*)&rb[0] = *(const float4*)&Bs[kk][tx * 8];
            *(float4*)&rb[4] = *(const float4*)&Bs[kk][tx * 8 + 4];
#pragma unroll
            for (int i = 0; i < 8; ++i)
#pragma unroll
                for (int j = 0; j < 8; ++j)
                    acc[i][j] = fmaf(ra[i], rb[j], acc[i][j]);
        }
        __syncthreads();
    }
#pragma unroll
    for (int i = 0; i < 8; ++i) {
        float* crow = C + (size_t)(bm + ty * 8 + i) * N + bn + tx * 8;
        float4 v0 = make_float4(acc[i][0], acc[i][1], acc[i][2], acc[i][3]);
        float4 v1 = make_float4(acc[i][4], acc[i][5], acc[i][6], acc[i][7]);
        *(float4*)(crow) = v0;
        *(float4*)(crow + 4) = v1;
    }
}

// ---------------------------------------------------------------------------
// RoPE (in place) + optional scale. One thread per rotation pair.
// Layout: rows (b*T+t), cols h*DK + d;  pairs (d, d+128), 128 freqs.
// ---------------------------------------------------------------------------
__global__ void rope_kernel(float* __restrict__ q, float scale)
{
    const int idx = blockIdx.x * blockDim.x + threadIdx.x;  // B*T*H*128
    const int i = idx & 127;
    const int h = (idx >> 7) & 7;
    const int row = idx >> 10;           // b*T + t
    const int t = row & (Tc - 1);
    const float inv = expf(-logf(10000.0f) * (float)i / 128.0f);
    float s, c;
    sincosf((float)t * inv, &s, &c);
    const size_t base = (size_t)row * (Hc * DKc) + h * DKc + i;
    const float x1 = q[base];
    const float x2 = q[base + 128];
    q[base]        = (x1 * c - x2 * s) * scale;
    q[base + 128]  = (x2 * c + x1 * s) * scale;
}

// ---------------------------------------------------------------------------
// scores[b,h,n,c,m] = (q_c . k_m) * Dmask   (q already scaled by DK^-1/2)
// grid.x = b*h*n (512), 256 threads, 64x64 output, K=256 in 4 slices of 64
// ---------------------------------------------------------------------------
__global__ __launch_bounds__(256) void scores_kernel(
    const float* __restrict__ q, const float* __restrict__ k,
    float* __restrict__ sc)
{
    __shared__ float qs[64][68];  // [d][c]
    __shared__ float ks[64][68];  // [d][m]
    const int bhn = blockIdx.x;
    const int n = bhn & 31, h = (bhn >> 5) & 7, b = bhn >> 8;
    const float logb = decay_logb(h);
    const int tid = threadIdx.x;
    const int tx = tid & 15, ty = tid >> 4;
    const size_t rowbase = (size_t)(b * Tc + n * Cc);

    float acc[4][4];
#pragma unroll
    for (int i = 0; i < 4; ++i)
#pragma unroll
        for (int j = 0; j < 4; ++j) acc[i][j] = 0.f;

    for (int d0 = 0; d0 < DKc; d0 += 64) {
#pragma unroll
        for (int r = 0; r < 4; ++r) {
            const int lin = tid + r * 256;
            const int c = lin >> 4;
            const int d4 = (lin & 15) * 4;
            float4 vq = *(const float4*)(q + (rowbase + c) * (Hc * DKc) + h * DKc + d0 + d4);
            qs[d4 + 0][c] = vq.x; qs[d4 + 1][c] = vq.y; qs[d4 + 2][c] = vq.z; qs[d4 + 3][c] = vq.w;
            float4 vk = *(const float4*)(k + (rowbase + c) * (Hc * DKc) + h * DKc + d0 + d4);
            ks[d4 + 0][c] = vk.x; ks[d4 + 1][c] = vk.y; ks[d4 + 2][c] = vk.z; ks[d4 + 3][c] = vk.w;
        }
        __syncthreads();
#pragma unroll
        for (int dd = 0; dd < 64; ++dd) {
            float ra[4], rb[4];
            *(float4*)ra = *(const float4*)&qs[dd][ty * 4];
            *(float4*)rb = *(const float4*)&ks[dd][tx * 4];
#pragma unroll
            for (int i = 0; i < 4; ++i)
#pragma unroll
                for (int j = 0; j < 4; ++j)
                    acc[i][j] = fmaf(ra[i], rb[j], acc[i][j]);
        }
        __syncthreads();
    }
#pragma unroll
    for (int i = 0; i < 4; ++i) {
        const int c = ty * 4 + i;
#pragma unroll
        for (int j = 0; j < 4; ++j) {
            const int m = tx * 4 + j;
            float val = (c >= m) ? acc[i][j] * expf(logb * (float)(c - m)) : 0.f;
            sc[((size_t)bhn * Cc + c) * Cc + m] = val;
        }
    }
}

// ---------------------------------------------------------------------------
// A_n[d,j] = sum_c k[c,d]*kdec[c]*v[c,j]   per (b,h,n)
// grid: x=jtile(8), y=dtile(4), z=bhn(512)
// ---------------------------------------------------------------------------
__global__ __launch_bounds__(256) void akern(
    const float* __restrict__ k, const float* __restrict__ v,
    float* __restrict__ S)
{
    __shared__ float ks[64][68];  // [c][d]
    __shared__ float vs[64][68];  // [c][j]
    const int bhn = blockIdx.z;
    const int n = bhn & 31, h = (bhn >> 5) & 7, b = bhn >> 8;
    const int d0 = blockIdx.y * 64;
    const int j0 = blockIdx.x * 64;
    const float logb = decay_logb(h);
    const int tid = threadIdx.x;
    const int tx = tid & 15, ty = tid >> 4;
    const size_t rowbase = (size_t)(b * Tc + n * Cc);

#pragma unroll
    for (int r = 0; r < 4; ++r) {
        const int lin = tid + r * 256;
        const int c = lin >> 4;
        const int x4 = (lin & 15) * 4;
        const float kdec = expf(logb * (float)(Cc - 1 - c));
        float4 vk = *(const float4*)(k + (rowbase + c) * (Hc * DKc) + h * DKc + d0 + x4);
        ks[c][x4 + 0] = vk.x * kdec; ks[c][x4 + 1] = vk.y * kdec;
        ks[c][x4 + 2] = vk.z * kdec; ks[c][x4 + 3] = vk.w * kdec;
        float4 vv = *(const float4*)(v + (rowbase + c) * (Hc * DVc) + h * DVc + j0 + x4);
        vs[c][x4 + 0] = vv.x; vs[c][x4 + 1] = vv.y;
        vs[c][x4 + 2] = vv.z; vs[c][x4 + 3] = vv.w;
    }
    __syncthreads();

    float acc[4][4];
#pragma unroll
    for (int i = 0; i < 4; ++i)
#pragma unroll
        for (int j = 0; j < 4; ++j) acc[i][j] = 0.f;
#pragma unroll
    for (int c = 0; c < 64; ++c) {
        float ra[4], rb[4];
        *(float4*)ra = *(const float4*)&ks[c][ty * 4];
        *(float4*)rb = *(const float4*)&vs[c][tx * 4];
#pragma unroll
        for (int i = 0; i < 4; ++i)
#pragma unroll
            for (int j = 0; j < 4; ++j)
                acc[i][j] = fmaf(ra[i], rb[j], acc[i][j]);
    }
#pragma unroll
    for (int i = 0; i < 4; ++i) {
        float* sp = S + ((size_t)bhn * DKc + d0 + ty * 4 + i) * DVc + j0 + tx * 4;
        float4 v0 = make_float4(acc[i][0], acc[i][1], acc[i][2], acc[i][3]);
        *(float4*)sp = v0;
    }
}

// ---------------------------------------------------------------------------
// Exclusive decay scan over chunks (in place on g_S):
//   out[n] = sum_{m<n} cdec^{n-1-m} * A[m]
// one thread per float4 of the (DK,DV) state; 32 sequential steps
// ---------------------------------------------------------------------------
__global__ void scan_kernel(float* __restrict__ S)
{
    const int idx = blockIdx.x * blockDim.x + threadIdx.x;  // 16 * 32768
    const int bh = idx >> 15;
    const int off4 = idx & 32767;
    const int h = bh & 7;
    const float cdec = expf(decay_logb(h) * (float)Cc);
    const size_t stride = (size_t)DKc * DVc;                // 131072
    float* base = S + (size_t)bh * Nc * stride + (size_t)off4 * 4;
    float4 s = make_float4(0.f, 0.f, 0.f, 0.f);
    for (int n = 0; n < Nc; ++n) {
        float4 a = *(float4*)(base + (size_t)n * stride);
        *(float4*)(base + (size_t)n * stride) = s;
        s.x = s.x * cdec + a.x; s.y = s.y * cdec + a.y;
        s.z = s.z * cdec + a.z; s.w = s.w * cdec + a.w;
    }
}

// ---------------------------------------------------------------------------
// o[c,j] = qdec[c]*sum_d q[c,d]*S[d,j] + sum_m sc[c,m]*v[m,j]
// grid: x=jtile(8), y=bhn(512). qdec folded into q on load.
// ---------------------------------------------------------------------------
__global__ __launch_bounds__(256) void okern(
    const float* __restrict__ q, const float* __restrict__ S,
    const float* __restrict__ sc, const float* __restrict__ v,
    float* __restrict__ o)
{
    __shared__ float a_s[64][68];
    __shared__ float b_s[64][68];
    const int bhn = blockIdx.y;
    const int n = bhn & 31, h = (bhn >> 5) & 7, b = bhn >> 8;
    const int j0 = blockIdx.x * 64;
    const float logb = decay_logb(h);
    const int tid = threadIdx.x;
    const int tx = tid & 15, ty = tid >> 4;
    const size_t rowbase = (size_t)(b * Tc + n * Cc);

    float acc[4][4];
#pragma unroll
    for (int i = 0; i < 4; ++i)
#pragma unroll
        for (int j = 0; j < 4; ++j) acc[i][j] = 0.f;

    // phase 1: inter-chunk  (q*qdec) @ S_prefix, K=256 in 4 slices
    for (int d0 = 0; d0 < DKc; d0 += 64) {
#pragma unroll
        for (int r = 0; r < 4; ++r) {
            const int lin = tid + r * 256;
            const int c = lin >> 4;
            const int x4 = (lin & 15) * 4;
            const float qdec = expf(logb * (float)(c + 1));
            float4 vq = *(const float4*)(q + (rowbase + c) * (Hc * DKc) + h * DKc + d0 + x4);
            a_s[x4 + 0][c] = vq.x * qdec; a_s[x4 + 1][c] = vq.y * qdec;
            a_s[x4 + 2][c] = vq.z * qdec; a_s[x4 + 3][c] = vq.w * qdec;
            // S tile rows d0+dd, cols j0+..  (dd = c index role here)
            float4 vsv = *(const float4*)(S + ((size_t)bhn * DKc + d0 + c) * DVc + j0 + x4);
            b_s[c][x4 + 0] = vsv.x; b_s[c][x4 + 1] = vsv.y;
            b_s[c][x4 + 2] = vsv.z; b_s[c][x4 + 3] = vsv.w;
        }
        __syncthreads();
#pragma unroll
        for (int dd = 0; dd < 64; ++dd) {
            float ra[4], rb[4];
            *(float4*)ra = *(const float4*)&a_s[dd][ty * 4];
            *(float4*)rb = *(const float4*)&b_s[dd][tx * 4];
#pragma unroll
            for (int i = 0; i < 4; ++i)
#pragma unroll
                for (int j = 0; j < 4; ++j)
                    acc[i][j] = fmaf(ra[i], rb[j], acc[i][j]);
        }
        __syncthreads();
    }

    // phase 2: intra-chunk  scores @ v, K=64
#pragma unroll
    for (int r = 0; r < 4; ++r) {
        const int lin = tid + r * 256;
        const int c = lin >> 4;
        const int x4 = (lin & 15) * 4;
        float4 vs4 = *(const float4*)(sc + ((size_t)bhn * Cc + c) * Cc + x4);
        a_s[x4 + 0][c] = vs4.x; a_s[x4 + 1][c] = vs4.y;
        a_s[x4 + 2][c] = vs4.z; a_s[x4 + 3][c] = vs4.w;
        float4 vv = *(const float4*)(v + (rowbase + c) * (Hc * DVc) + h * DVc + j0 + x4);
        b_s[c][x4 + 0] = vv.x; b_s[c][x4 + 1] = vv.y;
        b_s[c][x4 + 2] = vv.z; b_s[c][x4 + 3] = vv.w;
    }
    __syncthreads();
#pragma unroll
    for (int m = 0; m < 64; ++m) {
        float ra[4], rb[4];
        *(float4*)ra = *(const float4*)&a_s[m][ty * 4];
        *(float4*)rb = *(const float4*)&b_s[m][tx * 4];
#pragma unroll
        for (int i = 0; i < 4; ++i)
#pragma unroll
            for (int j = 0; j < 4; ++j)
                acc[i][j] = fmaf(ra[i], rb[j], acc[i][j]);
    }

#pragma unroll
    for (int i = 0; i < 4; ++i) {
        const int c = ty * 4 + i;
        float* op = o + (rowbase + c) * (Hc * DVc) + h * DVc + j0 + tx * 4;
        float4 v0 = make_float4(acc[i][0], acc[i][1], acc[i][2], acc[i][3]);
        *(float4*)op = v0;
    }
}

// ---------------------------------------------------------------------------
// RMS-norm over DV per (b,t,h), * g_norm_weight, gated by silu(g)
// grid = B*T*H blocks of 128 threads (each thread: 4 contiguous elems)
// ---------------------------------------------------------------------------
__global__ __launch_bounds__(128) void normgate(
    const float* __restrict__ o, const float* __restrict__ g,
    const float* __restrict__ w, float* __restrict__ out)
{
    const int row = blockIdx.x >> 3;
    const int h = blockIdx.x & 7;
    const size_t base = (size_t)row * (Hc * DVc) + h * DVc;
    const int tid = threadIdx.x;
    float4 ov = *(const float4*)(o + base + tid * 4);
    float ss = ov.x * ov.x + ov.y * ov.y + ov.z * ov.z + ov.w * ov.w;
#pragma unroll
    for (int off = 16; off > 0; off >>= 1)
        ss += __shfl_xor_sync(0xffffffffu, ss, off);
    __shared__ float red[4];
    if ((tid & 31) == 0) red[tid >> 5] = ss;
    __syncthreads();
    const float total = red[0] + red[1] + red[2] + red[3];
    const float r = rsqrtf(total / (float)DVc + 1e-5f);
    float4 gv = *(const float4*)(g + base + tid * 4);
    float4 wv = *(const float4*)(w + tid * 4);
    float4 res;
    res.x = ov.x * r * wv.x * (gv.x / (1.f + expf(-gv.x)));
    res.y = ov.y * r * wv.y * (gv.y / (1.f + expf(-gv.y)));
    res.z = ov.z * r * wv.z * (gv.z / (1.f + expf(-gv.z)));
    res.w = ov.w * r * wv.w * (gv.w / (1.f + expf(-gv.w)));
    *(float4*)(out + base + tid * 4) = res;
}

// ---------------------------------------------------------------------------
extern "C" void kernel_launch(void* const* d_in, const int* in_sizes, int n_in,
                              void* d_out, int out_size)
{
    const float* x  = (const float*)d_in[0];
    const float* Wq = (const float*)d_in[1];
    const float* Wk = (const float*)d_in[2];
    const float* Wv = (const float*)d_in[3];
    const float* Wg = (const float*)d_in[4];
    const float* Wo = (const float*)d_in[5];
    const float* gw = (const float*)d_in[6];
    float* out = (float*)d_out;

    float *qb, *kb, *vb, *gb, *scb, *Sb, *ob, *nb;
    cudaGetSymbolAddress((void**)&qb, g_q);
    cudaGetSymbolAddress((void**)&kb, g_k);
    cudaGetSymbolAddress((void**)&vb, g_v);
    cudaGetSymbolAddress((void**)&gb, g_g);
    cudaGetSymbolAddress((void**)&scb, g_sc);
    cudaGetSymbolAddress((void**)&Sb, g_S);
    cudaGetSymbolAddress((void**)&ob, g_o);
    cudaGetSymbolAddress((void**)&nb, g_n);

    // projections
    gemm_abt<<<dim3(16, 32), 256>>>(x, Wq, qb, Mrows, Hc * DKc, Dc);
    gemm_abt<<<dim3(16, 32), 256>>>(x, Wk, kb, Mrows, Hc * DKc, Dc);
    gemm_abt<<<dim3(32, 32), 256>>>(x, Wv, vb, Mrows, Hc * DVc, Dc);
    gemm_abt<<<dim3(32, 32), 256>>>(x, Wg, gb, Mrows, Hc * DVc, Dc);

    // rotary (+ q scale DK^-0.5)
    rope_kernel<<<(Mrows * Hc * 128) / 256, 256>>>(qb, 0.0625f);
    rope_kernel<<<(Mrows * Hc * 128) / 256, 256>>>(kb, 1.0f);

    // retention (parallel decomposition)
    scores_kernel<<<Bc * Hc * Nc, 256>>>(qb, kb, scb);
    akern<<<dim3(DVc / 64, DKc / 64, Bc * Hc * Nc), 256>>>(kb, vb, Sb);
    scan_kernel<<<(Bc * Hc * DKc * DVc / 4) / 256, 256>>>(Sb);
    okern<<<dim3(DVc / 64, Bc * Hc * Nc), 256>>>(qb, Sb, scb, vb, ob);

    // norm + gate, then output projection
    normgate<<<Mrows * Hc, 128>>>(ob, gb, gw, nb);
    gemm_abt<<<dim3(16, 32), 256>>>(nb, Wo, out, Mrows, Dc, Hc * DVc);
}

// round 3
// speedup vs baseline: 1.9110x; 1.9110x over previous
#include <cuda_runtime.h>
#include <cuda_bf16.h>
#include <math.h>
#include <stdint.h>

// Problem constants
#define Bc 2
#define Tc 2048
#define Dc 2048
#define Hc 8
#define DKc 256
#define DVc 512
#define Cc 64
#define Nc 32          // T / C
#define Mrows 4096     // B*T

// ---------------------------------------------------------------------------
// Scratch (device globals; no allocation allowed)
// ---------------------------------------------------------------------------
__device__ float g_q[(size_t)Mrows * (Hc * DKc)];
__device__ float g_k[(size_t)Mrows * (Hc * DKc)];
__device__ float g_v[(size_t)Mrows * (Hc * DVc)];
__device__ float g_g[(size_t)Mrows * (Hc * DVc)];
__device__ float g_sc[(size_t)Bc * Hc * Nc * Cc * Cc];
__device__ float g_S[(size_t)Bc * Hc * Nc * DKc * DVc];
__device__ float g_o[(size_t)Mrows * (Hc * DVc)];

// bf16 split buffers
__device__ __nv_bfloat16 g_xh[(size_t)Mrows * Dc];
__device__ __nv_bfloat16 g_xl[(size_t)Mrows * Dc];
__device__ __nv_bfloat16 g_wqh[(size_t)(Hc * DKc) * Dc];
__device__ __nv_bfloat16 g_wql[(size_t)(Hc * DKc) * Dc];
__device__ __nv_bfloat16 g_wkh[(size_t)(Hc * DKc) * Dc];
__device__ __nv_bfloat16 g_wkl[(size_t)(Hc * DKc) * Dc];
__device__ __nv_bfloat16 g_wvh[(size_t)(Hc * DVc) * Dc];
__device__ __nv_bfloat16 g_wvl[(size_t)(Hc * DVc) * Dc];
__device__ __nv_bfloat16 g_wgh[(size_t)(Hc * DVc) * Dc];
__device__ __nv_bfloat16 g_wgl[(size_t)(Hc * DVc) * Dc];
__device__ __nv_bfloat16 g_woh[(size_t)Dc * (Hc * DVc)];
__device__ __nv_bfloat16 g_wol[(size_t)Dc * (Hc * DVc)];
__device__ __nv_bfloat16 g_nh[(size_t)Mrows * (Hc * DVc)];
__device__ __nv_bfloat16 g_nl[(size_t)Mrows * (Hc * DVc)];

__device__ __forceinline__ float decay_logb(int h) {
    return logf(1.0f - exp2f(-5.0f - (float)h));
}

// ---------------------------------------------------------------------------
// PTX helpers
// ---------------------------------------------------------------------------
__device__ __forceinline__ void cpa16(void* s, const void* g) {
    unsigned sa = (unsigned)__cvta_generic_to_shared(s);
    asm volatile("cp.async.cg.shared.global [%0], [%1], 16;\n" :: "r"(sa), "l"(g));
}
__device__ __forceinline__ void ldsm4(uint32_t& r0, uint32_t& r1, uint32_t& r2, uint32_t& r3,
                                      const __nv_bfloat16* p) {
    unsigned a = (unsigned)__cvta_generic_to_shared(p);
    asm volatile("ldmatrix.sync.aligned.m8n8.x4.shared.b16 {%0,%1,%2,%3}, [%4];"
                 : "=r"(r0), "=r"(r1), "=r"(r2), "=r"(r3) : "r"(a));
}
__device__ __forceinline__ void ldsm2(uint32_t& r0, uint32_t& r1, const __nv_bfloat16* p) {
    unsigned a = (unsigned)__cvta_generic_to_shared(p);
    asm volatile("ldmatrix.sync.aligned.m8n8.x2.shared.b16 {%0,%1}, [%2];"
                 : "=r"(r0), "=r"(r1) : "r"(a));
}
__device__ __forceinline__ void mma16816(float* c, const uint32_t* a, const uint32_t* b) {
    asm volatile(
        "mma.sync.aligned.m16n8k16.row.col.f32.bf16.bf16.f32 "
        "{%0,%1,%2,%3}, {%4,%5,%6,%7}, {%8,%9}, {%0,%1,%2,%3};"
        : "+f"(c[0]), "+f"(c[1]), "+f"(c[2]), "+f"(c[3])
        : "r"(a[0]), "r"(a[1]), "r"(a[2]), "r"(a[3]), "r"(b[0]), "r"(b[1]));
}

// ---------------------------------------------------------------------------
// Split fp32 -> (hi, lo) bf16
// ---------------------------------------------------------------------------
__global__ void split_bf16(const float* __restrict__ in,
                           __nv_bfloat16* __restrict__ hi,
                           __nv_bfloat16* __restrict__ lo, int n4)
{
    int i = blockIdx.x * blockDim.x + threadIdx.x;
    if (i >= n4) return;
    float4 v = *(const float4*)(in + (size_t)i * 4);
    __nv_bfloat16 h0 = __float2bfloat16(v.x), h1 = __float2bfloat16(v.y);
    __nv_bfloat16 h2 = __float2bfloat16(v.z), h3 = __float2bfloat16(v.w);
    __nv_bfloat16 l0 = __float2bfloat16(v.x - __bfloat162float(h0));
    __nv_bfloat16 l1 = __float2bfloat16(v.y - __bfloat162float(h1));
    __nv_bfloat16 l2 = __float2bfloat16(v.z - __bfloat162float(h2));
    __nv_bfloat16 l3 = __float2bfloat16(v.w - __bfloat162float(h3));
    __nv_bfloat162* hp = (__nv_bfloat162*)(hi + (size_t)i * 4);
    __nv_bfloat162* lp = (__nv_bfloat162*)(lo + (size_t)i * 4);
    hp[0] = __nv_bfloat162(h0, h1); hp[1] = __nv_bfloat162(h2, h3);
    lp[0] = __nv_bfloat162(l0, l1); lp[1] = __nv_bfloat162(l2, l3);
}

// ---------------------------------------------------------------------------
// Tensor-core split-bf16 GEMM: C[M,N] = (Ah+Al)[M,K] @ (Bh+Bl)[N,K]^T
// 128x128x32 tile, 8 warps (2x4), warp tile 64x32, mma.m16n8k16
// smem rows padded to 40 bf16 (80B) -> conflict-free ldmatrix
// ---------------------------------------------------------------------------
#define GSM_ARR 5120            // 128*40 elems per array
#define GSM_STAGE 20480         // 4 arrays per stage
#define GSM_BYTES (2 * GSM_STAGE * 2)   // 81920

__global__ __launch_bounds__(256) void gemm_bf16_split(
    const __nv_bfloat16* __restrict__ Ah, const __nv_bfloat16* __restrict__ Al,
    const __nv_bfloat16* __restrict__ Bh, const __nv_bfloat16* __restrict__ Bl,
    float* __restrict__ C, int M, int N, int K)
{
    extern __shared__ __nv_bfloat16 sm[];
    const int tid = threadIdx.x;
    const int lane = tid & 31;
    const int warp = tid >> 5;
    const int wm = warp & 1;        // 0..1 -> 64-row slab
    const int wn = warp >> 1;       // 0..3 -> 32-col slab
    const int bm = blockIdx.y * 128;
    const int bn = blockIdx.x * 128;

    float acc[4][4][4];
#pragma unroll
    for (int i = 0; i < 4; ++i)
#pragma unroll
        for (int j = 0; j < 4; ++j)
#pragma unroll
            for (int r = 0; r < 4; ++r) acc[i][j][r] = 0.f;

    // loader mapping: each thread 2 chunks of 16B per array
    const int lrow = tid >> 1;            // 0..127
    const int lc0  = (tid & 1) * 2;       // chunk 0/2

    const int T = K >> 5;   // K/32

    // ---- prologue: load stage 0
    {
        const int k0 = 0;
        __nv_bfloat16* s = sm;   // stage 0
#pragma unroll
        for (int c = 0; c < 2; ++c) {
            const int ch = lc0 + c;
            cpa16(s + 0 * GSM_ARR + lrow * 40 + ch * 8, Ah + (size_t)(bm + lrow) * K + k0 + ch * 8);
            cpa16(s + 1 * GSM_ARR + lrow * 40 + ch * 8, Al + (size_t)(bm + lrow) * K + k0 + ch * 8);
            cpa16(s + 2 * GSM_ARR + lrow * 40 + ch * 8, Bh + (size_t)(bn + lrow) * K + k0 + ch * 8);
            cpa16(s + 3 * GSM_ARR + lrow * 40 + ch * 8, Bl + (size_t)(bn + lrow) * K + k0 + ch * 8);
        }
        asm volatile("cp.async.commit_group;");
    }

    for (int t = 0; t < T; ++t) {
        if (t + 1 < T) {
            const int k0 = (t + 1) << 5;
            __nv_bfloat16* s = sm + ((t + 1) & 1) * GSM_STAGE;
#pragma unroll
            for (int c = 0; c < 2; ++c) {
                const int ch = lc0 + c;
                cpa16(s + 0 * GSM_ARR + lrow * 40 + ch * 8, Ah + (size_t)(bm + lrow) * K + k0 + ch * 8);
                cpa16(s + 1 * GSM_ARR + lrow * 40 + ch * 8, Al + (size_t)(bm + lrow) * K + k0 + ch * 8);
                cpa16(s + 2 * GSM_ARR + lrow * 40 + ch * 8, Bh + (size_t)(bn + lrow) * K + k0 + ch * 8);
                cpa16(s + 3 * GSM_ARR + lrow * 40 + ch * 8, Bl + (size_t)(bn + lrow) * K + k0 + ch * 8);
            }
            asm volatile("cp.async.commit_group;");
            asm volatile("cp.async.wait_group 1;");
        } else {
            asm volatile("cp.async.wait_group 0;");
        }
        __syncthreads();

        const __nv_bfloat16* s = sm + (t & 1) * GSM_STAGE;
        const __nv_bfloat16* sAh = s + 0 * GSM_ARR;
        const __nv_bfloat16* sAl = s + 1 * GSM_ARR;
        const __nv_bfloat16* sBh = s + 2 * GSM_ARR;
        const __nv_bfloat16* sBl = s + 3 * GSM_ARR;

#pragma unroll
        for (int ks = 0; ks < 2; ++ks) {
            const int colb = ks * 16;
            // B fragments (4 n-tiles of 8)
            uint32_t bh[4][2], bl[4][2];
            const int brow = wn * 32 + (lane & 7);
            const int bcol = colb + ((lane >> 3) & 1) * 8;
#pragma unroll
            for (int j = 0; j < 4; ++j) {
                ldsm2(bh[j][0], bh[j][1], sBh + (brow + j * 8) * 40 + bcol);
                ldsm2(bl[j][0], bl[j][1], sBl + (brow + j * 8) * 40 + bcol);
            }
            const int arow = wm * 64 + (lane & 15);
            const int acol = colb + (lane >> 4) * 8;
#pragma unroll
            for (int i = 0; i < 4; ++i) {
                uint32_t ah[4], al[4];
                ldsm4(ah[0], ah[1], ah[2], ah[3], sAh + (arow + i * 16) * 40 + acol);
                ldsm4(al[0], al[1], al[2], al[3], sAl + (arow + i * 16) * 40 + acol);
#pragma unroll
                for (int j = 0; j < 4; ++j) {
                    mma16816(acc[i][j], ah, bh[j]);
                    mma16816(acc[i][j], ah, bl[j]);
                    mma16816(acc[i][j], al, bh[j]);
                }
            }
        }
        __syncthreads();
    }

    // epilogue
    const int crow = bm + wm * 64 + (lane >> 2);
    const int ccol = bn + wn * 32 + (lane & 3) * 2;
#pragma unroll
    for (int i = 0; i < 4; ++i) {
#pragma unroll
        for (int j = 0; j < 4; ++j) {
            float* p0 = C + (size_t)(crow + i * 16) * N + ccol + j * 8;
            float* p1 = C + (size_t)(crow + i * 16 + 8) * N + ccol + j * 8;
            p0[0] = acc[i][j][0]; p0[1] = acc[i][j][1];
            p1[0] = acc[i][j][2]; p1[1] = acc[i][j][3];
        }
    }
}

// ---------------------------------------------------------------------------
// RoPE (in place) + optional scale
// ---------------------------------------------------------------------------
__global__ void rope_kernel(float* __restrict__ q, float scale)
{
    const int idx = blockIdx.x * blockDim.x + threadIdx.x;
    const int i = idx & 127;
    const int h = (idx >> 7) & 7;
    const int row = idx >> 10;
    const int t = row & (Tc - 1);
    const float inv = expf(-logf(10000.0f) * (float)i / 128.0f);
    float s, c;
    sincosf((float)t * inv, &s, &c);
    const size_t base = (size_t)row * (Hc * DKc) + h * DKc + i;
    const float x1 = q[base];
    const float x2 = q[base + 128];
    q[base]        = (x1 * c - x2 * s) * scale;
    q[base + 128]  = (x2 * c + x1 * s) * scale;
}

// ---------------------------------------------------------------------------
// scores kernel (unchanged)
// ---------------------------------------------------------------------------
__global__ __launch_bounds__(256) void scores_kernel(
    const float* __restrict__ q, const float* __restrict__ k,
    float* __restrict__ sc)
{
    __shared__ float qs[64][68];
    __shared__ float ks[64][68];
    const int bhn = blockIdx.x;
    const int n = bhn & 31, h = (bhn >> 5) & 7, b = bhn >> 8;
    const float logb = decay_logb(h);
    const int tid = threadIdx.x;
    const int tx = tid & 15, ty = tid >> 4;
    const size_t rowbase = (size_t)(b * Tc + n * Cc);

    float acc[4][4];
#pragma unroll
    for (int i = 0; i < 4; ++i)
#pragma unroll
        for (int j = 0; j < 4; ++j) acc[i][j] = 0.f;

    for (int d0 = 0; d0 < DKc; d0 += 64) {
#pragma unroll
        for (int r = 0; r < 4; ++r) {
            const int lin = tid + r * 256;
            const int c = lin >> 4;
            const int d4 = (lin & 15) * 4;
            float4 vq = *(const float4*)(q + (rowbase + c) * (Hc * DKc) + h * DKc + d0 + d4);
            qs[d4 + 0][c] = vq.x; qs[d4 + 1][c] = vq.y; qs[d4 + 2][c] = vq.z; qs[d4 + 3][c] = vq.w;
            float4 vk = *(const float4*)(k + (rowbase + c) * (Hc * DKc) + h * DKc + d0 + d4);
            ks[d4 + 0][c] = vk.x; ks[d4 + 1][c] = vk.y; ks[d4 + 2][c] = vk.z; ks[d4 + 3][c] = vk.w;
        }
        __syncthreads();
#pragma unroll
        for (int dd = 0; dd < 64; ++dd) {
            float ra[4], rb[4];
            *(float4*)ra = *(const float4*)&qs[dd][ty * 4];
            *(float4*)rb = *(const float4*)&ks[dd][tx * 4];
#pragma unroll
            for (int i = 0; i < 4; ++i)
#pragma unroll
                for (int j = 0; j < 4; ++j)
                    acc[i][j] = fmaf(ra[i], rb[j], acc[i][j]);
        }
        __syncthreads();
    }
#pragma unroll
    for (int i = 0; i < 4; ++i) {
        const int c = ty * 4 + i;
#pragma unroll
        for (int j = 0; j < 4; ++j) {
            const int m = tx * 4 + j;
            float val = (c >= m) ? acc[i][j] * expf(logb * (float)(c - m)) : 0.f;
            sc[((size_t)bhn * Cc + c) * Cc + m] = val;
        }
    }
}

// ---------------------------------------------------------------------------
// A_n outer products (unchanged)
// ---------------------------------------------------------------------------
__global__ __launch_bounds__(256) void akern(
    const float* __restrict__ k, const float* __restrict__ v,
    float* __restrict__ S)
{
    __shared__ float ks[64][68];
    __shared__ float vs[64][68];
    const int bhn = blockIdx.z;
    const int n = bhn & 31, h = (bhn >> 5) & 7, b = bhn >> 8;
    const int d0 = blockIdx.y * 64;
    const int j0 = blockIdx.x * 64;
    const float logb = decay_logb(h);
    const int tid = threadIdx.x;
    const int tx = tid & 15, ty = tid >> 4;
    const size_t rowbase = (size_t)(b * Tc + n * Cc);

#pragma unroll
    for (int r = 0; r < 4; ++r) {
        const int lin = tid + r * 256;
        const int c = lin >> 4;
        const int x4 = (lin & 15) * 4;
        const float kdec = expf(logb * (float)(Cc - 1 - c));
        float4 vk = *(const float4*)(k + (rowbase + c) * (Hc * DKc) + h * DKc + d0 + x4);
        ks[c][x4 + 0] = vk.x * kdec; ks[c][x4 + 1] = vk.y * kdec;
        ks[c][x4 + 2] = vk.z * kdec; ks[c][x4 + 3] = vk.w * kdec;
        float4 vv = *(const float4*)(v + (rowbase + c) * (Hc * DVc) + h * DVc + j0 + x4);
        vs[c][x4 + 0] = vv.x; vs[c][x4 + 1] = vv.y;
        vs[c][x4 + 2] = vv.z; vs[c][x4 + 3] = vv.w;
    }
    __syncthreads();

    float acc[4][4];
#pragma unroll
    for (int i = 0; i < 4; ++i)
#pragma unroll
        for (int j = 0; j < 4; ++j) acc[i][j] = 0.f;
#pragma unroll
    for (int c = 0; c < 64; ++c) {
        float ra[4], rb[4];
        *(float4*)ra = *(const float4*)&ks[c][ty * 4];
        *(float4*)rb = *(const float4*)&vs[c][tx * 4];
#pragma unroll
        for (int i = 0; i < 4; ++i)
#pragma unroll
            for (int j = 0; j < 4; ++j)
                acc[i][j] = fmaf(ra[i], rb[j], acc[i][j]);
    }
#pragma unroll
    for (int i = 0; i < 4; ++i) {
        float* sp = S + ((size_t)bhn * DKc + d0 + ty * 4 + i) * DVc + j0 + tx * 4;
        float4 v0 = make_float4(acc[i][0], acc[i][1], acc[i][2], acc[i][3]);
        *(float4*)sp = v0;
    }
}

// ---------------------------------------------------------------------------
// Exclusive decay scan (unchanged)
// ---------------------------------------------------------------------------
__global__ void scan_kernel(float* __restrict__ S)
{
    const int idx = blockIdx.x * blockDim.x + threadIdx.x;
    const int bh = idx >> 15;
    const int off4 = idx & 32767;
    const int h = bh & 7;
    const float cdec = expf(decay_logb(h) * (float)Cc);
    const size_t stride = (size_t)DKc * DVc;
    float* base = S + (size_t)bh * Nc * stride + (size_t)off4 * 4;
    float4 s = make_float4(0.f, 0.f, 0.f, 0.f);
    for (int n = 0; n < Nc; ++n) {
        float4 a = *(float4*)(base + (size_t)n * stride);
        *(float4*)(base + (size_t)n * stride) = s;
        s.x = s.x * cdec + a.x; s.y = s.y * cdec + a.y;
        s.z = s.z * cdec + a.z; s.w = s.w * cdec + a.w;
    }
}

// ---------------------------------------------------------------------------
// okern (unchanged)
// ---------------------------------------------------------------------------
__global__ __launch_bounds__(256) void okern(
    const float* __restrict__ q, const float* __restrict__ S,
    const float* __restrict__ sc, const float* __restrict__ v,
    float* __restrict__ o)
{
    __shared__ float a_s[64][68];
    __shared__ float b_s[64][68];
    const int bhn = blockIdx.y;
    const int n = bhn & 31, h = (bhn >> 5) & 7, b = bhn >> 8;
    const int j0 = blockIdx.x * 64;
    const float logb = decay_logb(h);
    const int tid = threadIdx.x;
    const int tx = tid & 15, ty = tid >> 4;
    const size_t rowbase = (size_t)(b * Tc + n * Cc);

    float acc[4][4];
#pragma unroll
    for (int i = 0; i < 4; ++i)
#pragma unroll
        for (int j = 0; j < 4; ++j) acc[i][j] = 0.f;

    for (int d0 = 0; d0 < DKc; d0 += 64) {
#pragma unroll
        for (int r = 0; r < 4; ++r) {
            const int lin = tid + r * 256;
            const int c = lin >> 4;
            const int x4 = (lin & 15) * 4;
            const float qdec = expf(logb * (float)(c + 1));
            float4 vq = *(const float4*)(q + (rowbase + c) * (Hc * DKc) + h * DKc + d0 + x4);
            a_s[x4 + 0][c] = vq.x * qdec; a_s[x4 + 1][c] = vq.y * qdec;
            a_s[x4 + 2][c] = vq.z * qdec; a_s[x4 + 3][c] = vq.w * qdec;
            float4 vsv = *(const float4*)(S + ((size_t)bhn * DKc + d0 + c) * DVc + j0 + x4);
            b_s[c][x4 + 0] = vsv.x; b_s[c][x4 + 1] = vsv.y;
            b_s[c][x4 + 2] = vsv.z; b_s[c][x4 + 3] = vsv.w;
        }
        __syncthreads();
#pragma unroll
        for (int dd = 0; dd < 64; ++dd) {
            float ra[4], rb[4];
            *(float4*)ra = *(const float4*)&a_s[dd][ty * 4];
            *(float4*)rb = *(const float4*)&b_s[dd][tx * 4];
#pragma unroll
            for (int i = 0; i < 4; ++i)
#pragma unroll
                for (int j = 0; j < 4; ++j)
                    acc[i][j] = fmaf(ra[i], rb[j], acc[i][j]);
        }
        __syncthreads();
    }

#pragma unroll
    for (int r = 0; r < 4; ++r) {
        const int lin = tid + r * 256;
        const int c = lin >> 4;
        const int x4 = (lin & 15) * 4;
        float4 vs4 = *(const float4*)(sc + ((size_t)bhn * Cc + c) * Cc + x4);
        a_s[x4 + 0][c] = vs4.x; a_s[x4 + 1][c] = vs4.y;
        a_s[x4 + 2][c] = vs4.z; a_s[x4 + 3][c] = vs4.w;
        float4 vv = *(const float4*)(v + (rowbase + c) * (Hc * DVc) + h * DVc + j0 + x4);
        b_s[c][x4 + 0] = vv.x; b_s[c][x4 + 1] = vv.y;
        b_s[c][x4 + 2] = vv.z; b_s[c][x4 + 3] = vv.w;
    }
    __syncthreads();
#pragma unroll
    for (int m = 0; m < 64; ++m) {
        float ra[4], rb[4];
        *(float4*)ra = *(const float4*)&a_s[m][ty * 4];
        *(float4*)rb = *(const float4*)&b_s[m][tx * 4];
#pragma unroll
        for (int i = 0; i < 4; ++i)
#pragma unroll
            for (int j = 0; j < 4; ++j)
                acc[i][j] = fmaf(ra[i], rb[j], acc[i][j]);
    }

#pragma unroll
    for (int i = 0; i < 4; ++i) {
        const int c = ty * 4 + i;
        float* op = o + (rowbase + c) * (Hc * DVc) + h * DVc + j0 + tx * 4;
        float4 v0 = make_float4(acc[i][0], acc[i][1], acc[i][2], acc[i][3]);
        *(float4*)op = v0;
    }
}

// ---------------------------------------------------------------------------
// RMS-norm + silu gate; outputs bf16 split (hi, lo) for the final GEMM
// ---------------------------------------------------------------------------
__global__ __launch_bounds__(128) void normgate(
    const float* __restrict__ o, const float* __restrict__ g,
    const float* __restrict__ w,
    __nv_bfloat16* __restrict__ nh, __nv_bfloat16* __restrict__ nl)
{
    const int row = blockIdx.x >> 3;
    const int h = blockIdx.x & 7;
    const size_t base = (size_t)row * (Hc * DVc) + h * DVc;
    const int tid = threadIdx.x;
    float4 ov = *(const float4*)(o + base + tid * 4);
    float ss = ov.x * ov.x + ov.y * ov.y + ov.z * ov.z + ov.w * ov.w;
#pragma unroll
    for (int off = 16; off > 0; off >>= 1)
        ss += __shfl_xor_sync(0xffffffffu, ss, off);
    __shared__ float red[4];
    if ((tid & 31) == 0) red[tid >> 5] = ss;
    __syncthreads();
    const float total = red[0] + red[1] + red[2] + red[3];
    const float r = rsqrtf(total / (float)DVc + 1e-5f);
    float4 gv = *(const float4*)(g + base + tid * 4);
    float4 wv = *(const float4*)(w + tid * 4);
    float res[4];
    res[0] = ov.x * r * wv.x * (gv.x / (1.f + expf(-gv.x)));
    res[1] = ov.y * r * wv.y * (gv.y / (1.f + expf(-gv.y)));
    res[2] = ov.z * r * wv.z * (gv.z / (1.f + expf(-gv.z)));
    res[3] = ov.w * r * wv.w * (gv.w / (1.f + expf(-gv.w)));
    __nv_bfloat16 hh[4], ll[4];
#pragma unroll
    for (int e = 0; e < 4; ++e) {
        hh[e] = __float2bfloat16(res[e]);
        ll[e] = __float2bfloat16(res[e] - __bfloat162float(hh[e]));
    }
    __nv_bfloat162* hp = (__nv_bfloat162*)(nh + base + tid * 4);
    __nv_bfloat162* lp = (__nv_bfloat162*)(nl + base + tid * 4);
    hp[0] = __nv_bfloat162(hh[0], hh[1]); hp[1] = __nv_bfloat162(hh[2], hh[3]);
    lp[0] = __nv_bfloat162(ll[0], ll[1]); lp[1] = __nv_bfloat162(ll[2], ll[3]);
}

// ---------------------------------------------------------------------------
extern "C" void kernel_launch(void* const* d_in, const int* in_sizes, int n_in,
                              void* d_out, int out_size)
{
    const float* x  = (const float*)d_in[0];
    const float* Wq = (const float*)d_in[1];
    const float* Wk = (const float*)d_in[2];
    const float* Wv = (const float*)d_in[3];
    const float* Wg = (const float*)d_in[4];
    const float* Wo = (const float*)d_in[5];
    const float* gw = (const float*)d_in[6];
    float* out = (float*)d_out;

    float *qb, *kb, *vb, *gb, *scb, *Sb, *ob;
    cudaGetSymbolAddress((void**)&qb, g_q);
    cudaGetSymbolAddress((void**)&kb, g_k);
    cudaGetSymbolAddress((void**)&vb, g_v);
    cudaGetSymbolAddress((void**)&gb, g_g);
    cudaGetSymbolAddress((void**)&scb, g_sc);
    cudaGetSymbolAddress((void**)&Sb, g_S);
    cudaGetSymbolAddress((void**)&ob, g_o);

    __nv_bfloat16 *xh, *xl, *wqh, *wql, *wkh, *wkl, *wvh, *wvl, *wgh, *wgl, *woh, *wol, *nh, *nl;
    cudaGetSymbolAddress((void**)&xh, g_xh);   cudaGetSymbolAddress((void**)&xl, g_xl);
    cudaGetSymbolAddress((void**)&wqh, g_wqh); cudaGetSymbolAddress((void**)&wql, g_wql);
    cudaGetSymbolAddress((void**)&wkh, g_wkh); cudaGetSymbolAddress((void**)&wkl, g_wkl);
    cudaGetSymbolAddress((void**)&wvh, g_wvh); cudaGetSymbolAddress((void**)&wvl, g_wvl);
    cudaGetSymbolAddress((void**)&wgh, g_wgh); cudaGetSymbolAddress((void**)&wgl, g_wgl);
    cudaGetSymbolAddress((void**)&woh, g_woh); cudaGetSymbolAddress((void**)&wol, g_wol);
    cudaGetSymbolAddress((void**)&nh, g_nh);   cudaGetSymbolAddress((void**)&nl, g_nl);

    static int smem_set = 0;
    if (!smem_set) {
        cudaFuncSetAttribute(gemm_bf16_split,
                             cudaFuncAttributeMaxDynamicSharedMemorySize, GSM_BYTES);
        smem_set = 1;
    }

    const int TPB = 256;
    // splits
    split_bf16<<<(Mrows * Dc / 4 + TPB - 1) / TPB, TPB>>>(x, xh, xl, Mrows * Dc / 4);
    split_bf16<<<(Hc * DKc * Dc / 4 + TPB - 1) / TPB, TPB>>>(Wq, wqh, wql, Hc * DKc * Dc / 4);
    split_bf16<<<(Hc * DKc * Dc / 4 + TPB - 1) / TPB, TPB>>>(Wk, wkh, wkl, Hc * DKc * Dc / 4);
    split_bf16<<<(Hc * DVc * Dc / 4 + TPB - 1) / TPB, TPB>>>(Wv, wvh, wvl, Hc * DVc * Dc / 4);
    split_bf16<<<(Hc * DVc * Dc / 4 + TPB - 1) / TPB, TPB>>>(Wg, wgh, wgl, Hc * DVc * Dc / 4);
    split_bf16<<<(Dc * Hc * DVc / 4 + TPB - 1) / TPB, TPB>>>(Wo, woh, wol, Dc * Hc * DVc / 4);

    // projections on tensor cores
    gemm_bf16_split<<<dim3(16, 32), 256, GSM_BYTES>>>(xh, xl, wqh, wql, qb, Mrows, Hc * DKc, Dc);
    gemm_bf16_split<<<dim3(16, 32), 256, GSM_BYTES>>>(xh, xl, wkh, wkl, kb, Mrows, Hc * DKc, Dc);
    gemm_bf16_split<<<dim3(32, 32), 256, GSM_BYTES>>>(xh, xl, wvh, wvl, vb, Mrows, Hc * DVc, Dc);
    gemm_bf16_split<<<dim3(32, 32), 256, GSM_BYTES>>>(xh, xl, wgh, wgl, gb, Mrows, Hc * DVc, Dc);

    // rotary (+ q scale DK^-0.5)
    rope_kernel<<<(Mrows * Hc * 128) / 256, 256>>>(qb, 0.0625f);
    rope_kernel<<<(Mrows * Hc * 128) / 256, 256>>>(kb, 1.0f);

    // retention (parallel decomposition)
    scores_kernel<<<Bc * Hc * Nc, 256>>>(qb, kb, scb);
    akern<<<dim3(DVc / 64, DKc / 64, Bc * Hc * Nc), 256>>>(kb, vb, Sb);
    scan_kernel<<<(Bc * Hc * DKc * DVc / 4) / 256, 256>>>(Sb);
    okern<<<dim3(DVc / 64, Bc * Hc * Nc), 256>>>(qb, Sb, scb, vb, ob);

    // norm + gate (fused bf16 split), then output projection
    normgate<<<Mrows * Hc, 128>>>(ob, gb, gw, nh, nl);
    gemm_bf16_split<<<dim3(16, 32), 256, GSM_BYTES>>>(nh, nl, woh, wol, out, Mrows, Dc, Hc * DVc);
}